// round 11
// baseline (speedup 1.0000x reference)
#include <cuda_runtime.h>

// CTC batch cost, linear-domain forward. v5: no shared memory.
// Direct per-lane LDG of the 3 needed columns (blank, l0, l1) through a
// 16-step register ring; pipelined shfl; off-chain per-lane renorm (exact
// power-of-2, decision @ step 5 of each 8-step period, bias 2^80).
// One warp per batch item; lane l owns states 4l..4l+3.

#define Bc 256
#define Tc 512
#define Cc 128
#define Uc 48
#define BLANKC 127
#define FULLM 0xffffffffu
#define EBIAS 207          // 127 + 80: renorm target exponent 2^80
#define RING 16

__device__ __forceinline__ float lg2f_(float x) {
    float y; asm("lg2.approx.f32 %0, %1;" : "=f"(y) : "f"(x)); return y;
}
__device__ __forceinline__ int iclamp(int v, int lo, int hi) {
    return v < lo ? lo : (v > hi ? hi : v);
}
__device__ __forceinline__ float p2f(int e) {      // exact 2^e, e in [-126,126]
    return __int_as_float((unsigned)(127 + e) << 23);
}

// One timestep. Consumes pa3 (prev step's shfl result), issues next shfl early.
#define STEP(PB_, PL0_, PL1_, SCL_, SK1S_) do {                              \
    float a01 = a0 + a1;                                                     \
    float a23 = a2 + a3;                                                     \
    float a12 = a1 + a2;                                                     \
    float n3 = fmaf(sk3, a1, a23) * (PL1_);                                  \
    float pa3n = __shfl_up_sync(FULLM, n3, 1);                               \
    float n2 = a12 * (PB_);                                                  \
    float n1 = fmaf((SK1S_), pa3, a01) * (PL0_);                             \
    float n0 = fmaf((SCL_), pa3, a0) * (PB_);                                \
    a0 = n0; a1 = n1; a2 = n2; a3 = n3; pa3 = pa3n;                          \
} while (0)

__global__ __launch_bounds__(64)
void ctc_lin5_kernel(const void* __restrict__ yt_raw,
                     const float* __restrict__ y_pred,
                     float* __restrict__ out)
{
    const int lane = threadIdx.x & 31;
    const int w    = threadIdx.x >> 5;
    const int b    = blockIdx.x * 2 + w;

    // ---- label dtype probe (int64 vs int32), deterministic ----
    const long long* q64 = (const long long*)yt_raw;
    long long v0 = q64[lane * 2], v1 = q64[lane * 2 + 1];
    bool inr = (v0 >= 0 && v0 <= 127 && v1 >= 0 && v1 <= 127);
    bool is64 = __all_sync(FULLM, inr);
    const int* q32 = (const int*)yt_raw;

    // ---- per-lane labels + skip flags ----
    int u0 = 2 * lane, u1 = 2 * lane + 1;
    int cu0 = (u0 < Uc) ? u0 : 0;
    int cu1 = (u1 < Uc) ? u1 : 0;
    int l0 = is64 ? (int)q64[b * Uc + cu0] : q32[b * Uc + cu0];
    int l1 = is64 ? (int)q64[b * Uc + cu1] : q32[b * Uc + cu1];
    int lprev = __shfl_up_sync(FULLM, l1, 1);
    float sk1 = (u0 == 0 || l0 != lprev) ? 1.f : 0.f;
    float sk3 = (l1 != l0) ? 1.f : 0.f;

    const float* base = y_pred + (size_t)b * Tc * Cc;
    const float* qb = base + BLANKC;   // blank column (broadcast load)
    const float* q0 = base + l0;       // this lane's first-label column
    const float* q1 = base + l1;       // this lane's second-label column

    // ---- t = 0 init ----
    float a0 = (lane == 0) ? qb[0] : 0.f;
    float a1 = (lane == 0) ? q0[0] : 0.f;
    float a2 = 0.f, a3 = 0.f, pa3 = 0.f;
    int   eacc = 0;
    float scL  = (lane == 0) ? 0.f : 1.f;
    float scL0 = scL;
    float sk1s = sk1 * scL, sk1s0 = sk1s;

    // ---- 16-step register ring: slot s holds row t = (period base)+s ----
    float rb[RING], r0[RING], r1[RING];
#pragma unroll
    for (int j = 0; j < RING; j++) {           // prefill t = 1..16
        rb[j] = qb[(1 + j) * Cc];
        r0[j] = q0[(1 + j) * Cc];
        r1[j] = q1[(1 + j) * Cc];
    }

    // pending renorm state (computed @ j==5, applied after j==7)
    float sc_p = 1.f, scLn = scL, scL0n = scL;
    int   eacc_p = 0;

    // ---- main loop: periods k = 0..62 cover t = 1..504 ----
    const float* pbk = qb;   // period-base pointers (advance 8 rows / period)
    const float* p0k = q0;
    const float* p1k = q1;
    for (int k = 0; k < 63; k++) {
        const int sb = (k & 1) * 8;            // ring slot base for this period
        const bool last2 = (k >= 61);          // prefetch rows would pass T-1

#pragma unroll
        for (int j = 0; j < 8; j++) {
            const int s = sb + j;
            float pb  = rb[s];
            float pl0 = r0[s];
            float pl1 = r1[s];

            // prefetch row t = 1+8k+j+16 into the slot just consumed
            // (consumed again at period k+2; 16 steps of latency cover)
            if (!last2) {
                rb[s] = pbk[(1 + j + 16) * Cc];
                r0[s] = p0k[(1 + j + 16) * Cc];
                r1[s] = p1k[(1 + j + 16) * Cc];
            } else {
                int tp = 1 + 8 * k + j + 16; tp = tp > Tc - 1 ? Tc - 1 : tp;
                rb[s] = qb[tp * Cc];
                r0[s] = q0[tp * Cc];
                r1[s] = q1[tp * Cc];
            }

            if (j == 0) STEP(pb, pl0, pl1, scL0, sk1s0);
            else        STEP(pb, pl0, pl1, scL,  sk1s);

            if (j == 5) {                      // off-chain renorm decision
                float m5 = fmaxf(fmaxf(a0, a1), fmaxf(a2, a3));
                bool alive = (m5 > 0.f);
                int e = ((__float_as_int(m5) >> 23) & 0xff) - EBIAS;
                e = iclamp(e, -126, 126);
                int cand = eacc + e;
                int adopt = __reduce_min_sync(FULLM, alive ? cand : 0x7fffffff);
                int eaccN = alive ? cand : adopt;
                int dsc = alive ? -e : (eacc - adopt);
                sc_p = p2f(iclamp(dsc, -126, 126));
                int eLold = __shfl_up_sync(FULLM, eacc, 1);
                int eLnew = __shfl_up_sync(FULLM, eaccN, 1);
                int de0 = eLold - eaccN;
                int de  = eLnew - eaccN;
                scL0n = (lane == 0 || de0 < -126) ? 0.f : p2f(iclamp(de0, -126, 126));
                scLn  = (lane == 0 || de  < -126) ? 0.f : p2f(iclamp(de,  -126, 126));
                eacc_p = eaccN;
            }
        }

        // ---- apply pending renorm (exact power-of-2, error-free) ----
        a0 *= sc_p; a1 *= sc_p; a2 *= sc_p; a3 *= sc_p;
        eacc = eacc_p;
        scL = scLn; scL0 = scL0n;
        sk1s = sk1 * scL; sk1s0 = sk1 * scL0;

        pbk += 8 * Cc; p0k += 8 * Cc; p1k += 8 * Cc;
    }

    // ---- epilogue: period 63, t = 505..511 (slots 8..14), no renorm ----
#pragma unroll
    for (int j = 0; j < 7; j++) {
        const int s = 8 + j;
        if (j == 0) STEP(rb[s], r0[s], r1[s], scL0, sk1s0);
        else        STEP(rb[s], r0[s], r1[s], scL,  sk1s);
    }

    // ---- finish: true = stored * 2^eacc; states 95 (lane23,a3), 96 (lane24,a0)
    float v95 = __shfl_sync(FULLM, a3, 23); int e95 = __shfl_sync(FULLM, eacc, 23);
    float v96 = __shfl_sync(FULLM, a0, 24); int e96 = __shfl_sync(FULLM, eacc, 24);
    if (lane == 0) {
        int em = e95 > e96 ? e95 : e96;
        float s = ldexpf(v95, e95 - em) + ldexpf(v96, e96 - em);
        float ll2 = lg2f_(s) + (float)em;
        out[b] = -ll2 * 0.69314718055994530942f;
    }
}

extern "C" void kernel_launch(void* const* d_in, const int* in_sizes, int n_in,
                              void* d_out, int out_size)
{
    (void)in_sizes; (void)n_in; (void)out_size;
    const void*  y_true = d_in[0];
    const float* y_pred = (const float*)d_in[1];
    float* out = (float*)d_out;
    ctc_lin5_kernel<<<Bc / 2, 64>>>(y_true, y_pred, out);
}

// round 12
// speedup vs baseline: 4.4371x; 4.4371x over previous
#include <cuda_runtime.h>

// CTC batch cost, linear-domain forward. v6 = v5 with the register-ring fix:
// ALL ring indices are compile-time constants (period loop unrolled in pairs
// via DO_PERIOD(0)/DO_PERIOD(8)), so the 3x16 ring stays in registers instead
// of spilling to local memory (the v5 regression: regs 42, LDL/STL serial).
// One warp per batch item; lane l owns states 4l..4l+3.

#define Bc 256
#define Tc 512
#define Cc 128
#define Uc 48
#define BLANKC 127
#define FULLM 0xffffffffu
#define EBIAS 207          // 127 + 80: renorm target exponent 2^80
#define RING 16

__device__ __forceinline__ float lg2f_(float x) {
    float y; asm("lg2.approx.f32 %0, %1;" : "=f"(y) : "f"(x)); return y;
}
__device__ __forceinline__ int iclamp(int v, int lo, int hi) {
    return v < lo ? lo : (v > hi ? hi : v);
}
__device__ __forceinline__ float p2f(int e) {      // exact 2^e, e in [-126,126]
    return __int_as_float((unsigned)(127 + e) << 23);
}

// One timestep. Consumes pa3 (prev step's shfl result), issues next shfl early.
#define STEP(PB_, PL0_, PL1_, SCL_, SK1S_) do {                              \
    float a01 = a0 + a1;                                                     \
    float a23 = a2 + a3;                                                     \
    float a12 = a1 + a2;                                                     \
    float n3 = fmaf(sk3, a1, a23) * (PL1_);                                  \
    float pa3n = __shfl_up_sync(FULLM, n3, 1);                               \
    float n2 = a12 * (PB_);                                                  \
    float n1 = fmaf((SK1S_), pa3, a01) * (PL0_);                             \
    float n0 = fmaf((SCL_), pa3, a0) * (PB_);                                \
    a0 = n0; a1 = n1; a2 = n2; a3 = n3; pa3 = pa3n;                          \
} while (0)

// One 8-step period. SB must be a LITERAL (0 or 8) so ring indices are
// compile-time constants after unroll. Uses/updates: k, ring, pointers,
// alpha state, renorm state. Advances period-base pointers at the end.
#define DO_PERIOD(SB) do {                                                   \
    const bool last2 = (k >= 61);                                            \
    _Pragma("unroll")                                                        \
    for (int j = 0; j < 8; j++) {                                            \
        float pb  = rb[(SB) + j];                                            \
        float pl0 = r0[(SB) + j];                                            \
        float pl1 = r1[(SB) + j];                                            \
        if (!last2) {                                                        \
            rb[(SB) + j] = pbk[(1 + j + 16) * Cc];                           \
            r0[(SB) + j] = p0k[(1 + j + 16) * Cc];                           \
            r1[(SB) + j] = p1k[(1 + j + 16) * Cc];                           \
        } else {                                                             \
            int tp = 1 + 8 * k + j + 16; tp = tp > Tc - 1 ? Tc - 1 : tp;     \
            rb[(SB) + j] = qb[tp * Cc];                                      \
            r0[(SB) + j] = q0[tp * Cc];                                      \
            r1[(SB) + j] = q1[tp * Cc];                                      \
        }                                                                    \
        if (j == 0) STEP(pb, pl0, pl1, scL0, sk1s0);                         \
        else        STEP(pb, pl0, pl1, scL,  sk1s);                          \
        if (j == 5) {                      /* off-chain renorm decision */   \
            float m5 = fmaxf(fmaxf(a0, a1), fmaxf(a2, a3));                  \
            bool alive = (m5 > 0.f);                                         \
            int e = ((__float_as_int(m5) >> 23) & 0xff) - EBIAS;             \
            e = iclamp(e, -126, 126);                                        \
            int cand = eacc + e;                                             \
            int adopt = __reduce_min_sync(FULLM, alive ? cand : 0x7fffffff); \
            int eaccN = alive ? cand : adopt;                                \
            int dsc = alive ? -e : (eacc - adopt);                           \
            sc_p = p2f(iclamp(dsc, -126, 126));                              \
            int eLold = __shfl_up_sync(FULLM, eacc, 1);                      \
            int eLnew = __shfl_up_sync(FULLM, eaccN, 1);                     \
            int de0 = eLold - eaccN;                                         \
            int de  = eLnew - eaccN;                                         \
            scL0n = (lane == 0 || de0 < -126) ? 0.f                          \
                                              : p2f(iclamp(de0, -126, 126)); \
            scLn  = (lane == 0 || de  < -126) ? 0.f                          \
                                              : p2f(iclamp(de,  -126, 126)); \
            eacc_p = eaccN;                                                  \
        }                                                                    \
    }                                                                        \
    a0 *= sc_p; a1 *= sc_p; a2 *= sc_p; a3 *= sc_p;                          \
    eacc = eacc_p;                                                           \
    scL = scLn; scL0 = scL0n;                                                \
    sk1s = sk1 * scL; sk1s0 = sk1 * scL0;                                    \
    pbk += 8 * Cc; p0k += 8 * Cc; p1k += 8 * Cc;                             \
} while (0)

__global__ __launch_bounds__(64)
void ctc_lin6_kernel(const void* __restrict__ yt_raw,
                     const float* __restrict__ y_pred,
                     float* __restrict__ out)
{
    const int lane = threadIdx.x & 31;
    const int w    = threadIdx.x >> 5;
    const int b    = blockIdx.x * 2 + w;

    // ---- label dtype probe (int64 vs int32), deterministic ----
    const long long* q64 = (const long long*)yt_raw;
    long long v0 = q64[lane * 2], v1 = q64[lane * 2 + 1];
    bool inr = (v0 >= 0 && v0 <= 127 && v1 >= 0 && v1 <= 127);
    bool is64 = __all_sync(FULLM, inr);
    const int* q32 = (const int*)yt_raw;

    // ---- per-lane labels + skip flags ----
    int u0 = 2 * lane, u1 = 2 * lane + 1;
    int cu0 = (u0 < Uc) ? u0 : 0;
    int cu1 = (u1 < Uc) ? u1 : 0;
    int l0 = is64 ? (int)q64[b * Uc + cu0] : q32[b * Uc + cu0];
    int l1 = is64 ? (int)q64[b * Uc + cu1] : q32[b * Uc + cu1];
    int lprev = __shfl_up_sync(FULLM, l1, 1);
    float sk1 = (u0 == 0 || l0 != lprev) ? 1.f : 0.f;
    float sk3 = (l1 != l0) ? 1.f : 0.f;

    const float* base = y_pred + (size_t)b * Tc * Cc;
    const float* qb = base + BLANKC;   // blank column (broadcast load)
    const float* q0 = base + l0;       // this lane's first-label column
    const float* q1 = base + l1;       // this lane's second-label column

    // ---- t = 0 init ----
    float a0 = (lane == 0) ? qb[0] : 0.f;
    float a1 = (lane == 0) ? q0[0] : 0.f;
    float a2 = 0.f, a3 = 0.f, pa3 = 0.f;
    int   eacc = 0;
    float scL  = (lane == 0) ? 0.f : 1.f;
    float scL0 = scL;
    float sk1s = sk1 * scL, sk1s0 = sk1s;

    // ---- 16-step register ring (statically indexed everywhere) ----
    float rb[RING], r0[RING], r1[RING];
#pragma unroll
    for (int j = 0; j < RING; j++) {           // prefill t = 1..16
        rb[j] = qb[(1 + j) * Cc];
        r0[j] = q0[(1 + j) * Cc];
        r1[j] = q1[(1 + j) * Cc];
    }

    // pending renorm state (computed @ j==5, applied after j==7)
    float sc_p = 1.f, scLn = scL, scL0n = scL;
    int   eacc_p = 0;

    // ---- main loop: periods 0..61 in pairs (SB literal 0 / 8) ----
    const float* pbk = qb;
    const float* p0k = q0;
    const float* p1k = q1;
    for (int k = 0; k < 62; ) {
        DO_PERIOD(0);  k++;
        DO_PERIOD(8);  k++;
    }
    // ---- period 62 (SB=0) ----
    {
        int k = 62;
        DO_PERIOD(0);
    }

    // ---- epilogue: period 63, t = 505..511 (slots 8..14), no renorm ----
#pragma unroll
    for (int j = 0; j < 7; j++) {
        if (j == 0) STEP(rb[8 + j], r0[8 + j], r1[8 + j], scL0, sk1s0);
        else        STEP(rb[8 + j], r0[8 + j], r1[8 + j], scL,  sk1s);
    }

    // ---- finish: true = stored * 2^eacc; states 95 (lane23,a3), 96 (lane24,a0)
    float v95 = __shfl_sync(FULLM, a3, 23); int e95 = __shfl_sync(FULLM, eacc, 23);
    float v96 = __shfl_sync(FULLM, a0, 24); int e96 = __shfl_sync(FULLM, eacc, 24);
    if (lane == 0) {
        int em = e95 > e96 ? e95 : e96;
        float s = ldexpf(v95, e95 - em) + ldexpf(v96, e96 - em);
        float ll2 = lg2f_(s) + (float)em;
        out[b] = -ll2 * 0.69314718055994530942f;
    }
}

extern "C" void kernel_launch(void* const* d_in, const int* in_sizes, int n_in,
                              void* d_out, int out_size)
{
    (void)in_sizes; (void)n_in; (void)out_size;
    const void*  y_true = d_in[0];
    const float* y_pred = (const float*)d_in[1];
    float* out = (float*)d_out;
    ctc_lin6_kernel<<<Bc / 2, 64>>>(y_true, y_pred, out);
}